// round 2
// baseline (speedup 1.0000x reference)
#include <cuda_runtime.h>
#include <math.h>

#define ROWS_PER_BLOCK 64
#define THREADS 64
#define NF 128
#define NG 64
#define NM 3
#define PAD 129

#define HALF_LOG_2PI 0.9189385332046727f
#define L2E 1.4426950408889634f
#define LN2 0.6931471805599453f

__device__ __forceinline__ float ex2f(float x) {
    float y; asm("ex2.approx.ftz.f32 %0, %1;" : "=f"(y) : "f"(x)); return y;
}
__device__ __forceinline__ float lg2f(float x) {
    float y; asm("lg2.approx.ftz.f32 %0, %1;" : "=f"(y) : "f"(x)); return y;
}

__global__ void __launch_bounds__(THREADS)
spn_kernel(const float* __restrict__ x,
           const int* __restrict__ perm,
           const float* __restrict__ means,
           const float* __restrict__ stds,
           const float* __restrict__ sumw,
           float* __restrict__ out,
           int B)
{
    // Static shared memory: 4096 + 512 + 64*129*4 = 37632 B (< 48 KB default)
    __shared__ float4 sPack[NG * 4];
    __shared__ int2   sIdx[NG];
    __shared__ float  sx[ROWS_PER_BLOCK * PAD];

    const int t = threadIdx.x;

    // ---- Phase A: per-block coefficient prep, one thread per group g
    {
        const int g  = t;            // THREADS == NG == 64
        const int j0 = 2 * g, j1 = 2 * g + 1;
        const int u = perm[j0];
        const int v = perm[j1];
        sIdx[g] = make_int2(u, v);

        // log_softmax of sum_weights[g, :, 0] over the MULT axis
        float sw0 = sumw[g * 3 + 0];
        float sw1 = sumw[g * 3 + 1];
        float sw2 = sumw[g * 3 + 2];
        float mw  = fmaxf(sw0, fmaxf(sw1, sw2));
        float lse = mw + logf(expf(sw0 - mw) + expf(sw1 - mw) + expf(sw2 - mw));

        float C[3];
        #pragma unroll
        for (int m = 0; m < NM; ++m) {
            float mu0 = means[j0 * 3 + m], sd0 = stds[j0 * 3 + m];
            float mu1 = means[j1 * 3 + m], sd1 = stds[j1 * 3 + m];
            float is0 = 1.0f / sd0;
            float is1 = 1.0f / sd1;
            float is0sq = is0 * is0;
            float is1sq = is1 * is1;
            float a0 = -0.5f * is0sq;
            float b0 = mu0 * is0sq;
            float c0 = -0.5f * mu0 * mu0 * is0sq - logf(sd0) - HALF_LOG_2PI;
            float a1 = -0.5f * is1sq;
            float b1 = mu1 * is1sq;
            float c1 = -0.5f * mu1 * mu1 * is1sq - logf(sd1) - HALF_LOG_2PI;
            float logw = (m == 0 ? sw0 : (m == 1 ? sw1 : sw2)) - lse;
            C[m] = (c0 + c1 + logw) * L2E;
            sPack[g * 4 + m] = make_float4(a0 * L2E, b0 * L2E, a1 * L2E, b1 * L2E);
        }
        sPack[g * 4 + 3] = make_float4(C[0], C[1], C[2], 0.0f);
    }

    // ---- Phase B: stage the block's x tile into padded smem (coalesced LDG.128)
    const int rowBase = blockIdx.x * ROWS_PER_BLOCK;
    const float4* xg = reinterpret_cast<const float4*>(x) + (long long)rowBase * (NF / 4);
    #pragma unroll
    for (int i = 0; i < (ROWS_PER_BLOCK * NF / 4) / THREADS; ++i) {
        int idx = i * THREADS + t;                 // 0 .. 2047
        float4 v4 = xg[idx];
        int r = idx >> 5;                          // 32 float4 per row
        int c = (idx & 31) << 2;
        float* dst = &sx[r * PAD + c];
        dst[0] = v4.x; dst[1] = v4.y; dst[2] = v4.z; dst[3] = v4.w;
    }
    __syncthreads();

    // ---- Phase C: one thread per row
    const int gRow = rowBase + t;
    if (gRow >= B) return;
    const float* xr = &sx[t * PAD];

    float accM = 0.0f;
    float accL = 0.0f;

    #pragma unroll 4
    for (int g = 0; g < NG; ++g) {
        int2 uv = sIdx[g];
        float x0 = xr[uv.x];
        float x1 = xr[uv.y];
        float x0s = x0 * x0;
        float x1s = x1 * x1;

        float4 k0 = sPack[g * 4 + 0];
        float4 k1 = sPack[g * 4 + 1];
        float4 k2 = sPack[g * 4 + 2];
        float4 kc = sPack[g * 4 + 3];

        float p0 = fmaf(k0.x, x0s, fmaf(k0.y, x0, fmaf(k0.z, x1s, fmaf(k0.w, x1, kc.x))));
        float p1 = fmaf(k1.x, x0s, fmaf(k1.y, x0, fmaf(k1.z, x1s, fmaf(k1.w, x1, kc.y))));
        float p2 = fmaf(k2.x, x0s, fmaf(k2.y, x0, fmaf(k2.z, x1s, fmaf(k2.w, x1, kc.z))));

        float mx = fmaxf(p0, fmaxf(p1, p2));
        float s  = ex2f(p0 - mx) + ex2f(p1 - mx) + ex2f(p2 - mx);
        accM += mx;
        accL += lg2f(s);
    }

    out[gRow] = (accM + accL) * LN2;
}

extern "C" void kernel_launch(void* const* d_in, const int* in_sizes, int n_in,
                              void* d_out, int out_size)
{
    const float* x     = (const float*)d_in[0];
    const int*   perm  = (const int*)d_in[1];
    const float* means = (const float*)d_in[2];
    const float* stds  = (const float*)d_in[3];
    const float* sumw  = (const float*)d_in[4];
    float* out = (float*)d_out;

    int B = in_sizes[0] / NF;

    dim3 grid((B + ROWS_PER_BLOCK - 1) / ROWS_PER_BLOCK);
    spn_kernel<<<grid, THREADS>>>(x, perm, means, stds, sumw, out, B);
}

// round 3
// speedup vs baseline: 1.0974x; 1.0974x over previous
#include <cuda_runtime.h>
#include <math.h>

#define THREADS 256
#define ROWS_PER_BLOCK 64
#define NF 128
#define NG 64
#define NM 3
#define PAD 129
#define CHUNKS 4
#define GPC 16   // groups per chunk

#define HALF_LOG_2PI 0.9189385332046727f
#define L2E 1.4426950408889634f
#define LN2 0.6931471805599453f

__device__ __forceinline__ float ex2f(float x) {
    float y; asm("ex2.approx.ftz.f32 %0, %1;" : "=f"(y) : "f"(x)); return y;
}
__device__ __forceinline__ float lg2f(float x) {
    float y; asm("lg2.approx.ftz.f32 %0, %1;" : "=f"(y) : "f"(x)); return y;
}

__global__ void __launch_bounds__(THREADS, 4)
spn_kernel(const float* __restrict__ x,
           const int* __restrict__ perm,
           const float* __restrict__ means,
           const float* __restrict__ stds,
           const float* __restrict__ sumw,
           float* __restrict__ out,
           int B)
{
    // Static smem: 4096 + 512 + 33024 + 1024 = 38656 B (< 48 KB)
    __shared__ float4 sPack[NG * 4];
    __shared__ int2   sIdx[NG];
    __shared__ float  sx[ROWS_PER_BLOCK * PAD];
    __shared__ float  sRed[CHUNKS * ROWS_PER_BLOCK];

    const int t = threadIdx.x;

    // ---- Phase A: per-block coefficient prep, threads 0..63, one per group
    if (t < NG) {
        const int g  = t;
        const int j0 = 2 * g, j1 = 2 * g + 1;
        sIdx[g] = make_int2(perm[j0], perm[j1]);

        float sw0 = sumw[g * 3 + 0];
        float sw1 = sumw[g * 3 + 1];
        float sw2 = sumw[g * 3 + 2];
        float mw  = fmaxf(sw0, fmaxf(sw1, sw2));
        float lse = mw + logf(expf(sw0 - mw) + expf(sw1 - mw) + expf(sw2 - mw));

        float C[3];
        #pragma unroll
        for (int m = 0; m < NM; ++m) {
            float mu0 = means[j0 * 3 + m], sd0 = stds[j0 * 3 + m];
            float mu1 = means[j1 * 3 + m], sd1 = stds[j1 * 3 + m];
            float is0 = 1.0f / sd0;
            float is1 = 1.0f / sd1;
            float is0sq = is0 * is0;
            float is1sq = is1 * is1;
            float a0 = -0.5f * is0sq;
            float b0 = mu0 * is0sq;
            float c0 = -0.5f * mu0 * mu0 * is0sq - logf(sd0) - HALF_LOG_2PI;
            float a1 = -0.5f * is1sq;
            float b1 = mu1 * is1sq;
            float c1 = -0.5f * mu1 * mu1 * is1sq - logf(sd1) - HALF_LOG_2PI;
            float logw = (m == 0 ? sw0 : (m == 1 ? sw1 : sw2)) - lse;
            C[m] = (c0 + c1 + logw) * L2E;
            // quadratic in Horner form: p = ((a0*x0+b0)*x0) + ((a1*x1+b1)*x1) + C
            sPack[g * 4 + m] = make_float4(a0 * L2E, b0 * L2E, a1 * L2E, b1 * L2E);
        }
        sPack[g * 4 + 3] = make_float4(C[0], C[1], C[2], 0.0f);
    }

    // ---- Phase B: stage x tile into padded smem (coalesced LDG.128)
    const int rowBase = blockIdx.x * ROWS_PER_BLOCK;
    const float4* xg = reinterpret_cast<const float4*>(x) + (long long)rowBase * (NF / 4);
    #pragma unroll
    for (int i = 0; i < (ROWS_PER_BLOCK * NF / 4) / THREADS; ++i) {
        int idx = i * THREADS + t;                 // 0 .. 2047
        float4 v4 = xg[idx];
        int r = idx >> 5;                          // 32 float4 per row
        int c = (idx & 31) << 2;
        float* dst = &sx[r * PAD + c];
        dst[0] = v4.x; dst[1] = v4.y; dst[2] = v4.z; dst[3] = v4.w;
    }
    __syncthreads();

    // ---- Phase C: 4 threads per row, each handles 16 groups.
    // Warp layout: chunk = t>>6 is warp-uniform; rows consecutive within warp.
    const int chunk = t >> 6;
    const int row   = t & 63;
    const float* xr = &sx[row * PAD];

    float accM = 0.0f;
    float accL = 0.0f;

    const int gBase = chunk * GPC;
    #pragma unroll 4
    for (int i = 0; i < GPC; ++i) {
        const int g = gBase + i;
        int2 uv = sIdx[g];
        float x0 = xr[uv.x];
        float x1 = xr[uv.y];

        float4 k0 = sPack[g * 4 + 0];
        float4 k1 = sPack[g * 4 + 1];
        float4 k2 = sPack[g * 4 + 2];
        float4 kc = sPack[g * 4 + 3];

        float q00 = fmaf(k0.x, x0, k0.y);
        float q01 = fmaf(k0.z, x1, k0.w);
        float q10 = fmaf(k1.x, x0, k1.y);
        float q11 = fmaf(k1.z, x1, k1.w);
        float q20 = fmaf(k2.x, x0, k2.y);
        float q21 = fmaf(k2.z, x1, k2.w);

        float p0 = fmaf(q01, x1, fmaf(q00, x0, kc.x));
        float p1 = fmaf(q11, x1, fmaf(q10, x0, kc.y));
        float p2 = fmaf(q21, x1, fmaf(q20, x0, kc.z));

        float mx = fmaxf(p0, fmaxf(p1, p2));
        float s  = ex2f(p0 - mx) + ex2f(p1 - mx) + ex2f(p2 - mx);
        accM += mx;
        accL += lg2f(s);
    }

    sRed[chunk * ROWS_PER_BLOCK + row] = accM + accL;
    __syncthreads();

    // ---- Phase D: threads 0..63 combine the 4 chunk partials per row
    if (t < ROWS_PER_BLOCK) {
        float v = sRed[t]
                + sRed[ROWS_PER_BLOCK + t]
                + sRed[2 * ROWS_PER_BLOCK + t]
                + sRed[3 * ROWS_PER_BLOCK + t];
        int gRow = rowBase + t;
        if (gRow < B) out[gRow] = v * LN2;
    }
}

extern "C" void kernel_launch(void* const* d_in, const int* in_sizes, int n_in,
                              void* d_out, int out_size)
{
    const float* x     = (const float*)d_in[0];
    const int*   perm  = (const int*)d_in[1];
    const float* means = (const float*)d_in[2];
    const float* stds  = (const float*)d_in[3];
    const float* sumw  = (const float*)d_in[4];
    float* out = (float*)d_out;

    int B = in_sizes[0] / NF;

    dim3 grid((B + ROWS_PER_BLOCK - 1) / ROWS_PER_BLOCK);
    spn_kernel<<<grid, THREADS>>>(x, perm, means, stds, sumw, out, B);
}

// round 4
// speedup vs baseline: 1.1879x; 1.0824x over previous
#include <cuda_runtime.h>
#include <math.h>

#define THREADS 256
#define ROWS_PER_BLOCK 64
#define NF 128
#define NG 64
#define NM 3
#define PAD 129
#define CHUNKS 8
#define GPC 8    // groups per chunk (NG / CHUNKS)

#define HALF_LOG_2PI 0.9189385332046727f
#define L2E 1.4426950408889634f
#define LN2 0.6931471805599453f

__device__ __forceinline__ float ex2f(float x) {
    float y; asm("ex2.approx.ftz.f32 %0, %1;" : "=f"(y) : "f"(x)); return y;
}
__device__ __forceinline__ float lg2f(float x) {
    float y; asm("lg2.approx.ftz.f32 %0, %1;" : "=f"(y) : "f"(x)); return y;
}

__global__ void __launch_bounds__(THREADS, 4)
spn_kernel(const float* __restrict__ x,
           const int* __restrict__ perm,
           const float* __restrict__ means,
           const float* __restrict__ stds,
           const float* __restrict__ sumw,
           float* __restrict__ out,
           int B)
{
    // Static smem: 4096 + 512 + 33024 + 2048 = 39680 B (< 48 KB)
    __shared__ float4 sPack[NG * 4];
    __shared__ int2   sIdx[NG];
    __shared__ float  sx[ROWS_PER_BLOCK * PAD];
    __shared__ float  sRed[CHUNKS * ROWS_PER_BLOCK];

    const int t = threadIdx.x;

    // ---- Phase A: per-block coefficient prep, threads 0..63, one per group
    if (t < NG) {
        const int g  = t;
        const int j0 = 2 * g, j1 = 2 * g + 1;
        sIdx[g] = make_int2(perm[j0], perm[j1]);

        float sw0 = sumw[g * 3 + 0];
        float sw1 = sumw[g * 3 + 1];
        float sw2 = sumw[g * 3 + 2];
        float mw  = fmaxf(sw0, fmaxf(sw1, sw2));
        float lse = mw + logf(expf(sw0 - mw) + expf(sw1 - mw) + expf(sw2 - mw));

        float C[3];
        #pragma unroll
        for (int m = 0; m < NM; ++m) {
            float mu0 = means[j0 * 3 + m], sd0 = stds[j0 * 3 + m];
            float mu1 = means[j1 * 3 + m], sd1 = stds[j1 * 3 + m];
            float is0 = 1.0f / sd0;
            float is1 = 1.0f / sd1;
            float is0sq = is0 * is0;
            float is1sq = is1 * is1;
            float a0 = -0.5f * is0sq;
            float b0 = mu0 * is0sq;
            float c0 = -0.5f * mu0 * mu0 * is0sq - logf(sd0) - HALF_LOG_2PI;
            float a1 = -0.5f * is1sq;
            float b1 = mu1 * is1sq;
            float c1 = -0.5f * mu1 * mu1 * is1sq - logf(sd1) - HALF_LOG_2PI;
            float logw = (m == 0 ? sw0 : (m == 1 ? sw1 : sw2)) - lse;
            C[m] = (c0 + c1 + logw) * L2E;
            sPack[g * 4 + m] = make_float4(a0 * L2E, b0 * L2E, a1 * L2E, b1 * L2E);
        }
        sPack[g * 4 + 3] = make_float4(C[0], C[1], C[2], 0.0f);
    }

    // ---- Phase B: stage x tile into padded smem (coalesced LDG.128)
    const int rowBase = blockIdx.x * ROWS_PER_BLOCK;
    const float4* xg = reinterpret_cast<const float4*>(x) + (long long)rowBase * (NF / 4);
    #pragma unroll
    for (int i = 0; i < (ROWS_PER_BLOCK * NF / 4) / THREADS; ++i) {
        int idx = i * THREADS + t;                 // 0 .. 2047
        float4 v4 = xg[idx];
        int r = idx >> 5;                          // 32 float4 per row
        int c = (idx & 31) << 2;
        float* dst = &sx[r * PAD + c];
        dst[0] = v4.x; dst[1] = v4.y; dst[2] = v4.z; dst[3] = v4.w;
    }
    __syncthreads();

    // ---- Phase C: each warp = one chunk of 8 groups; each lane handles 2 rows
    // (lane and lane+32; both conflict-free: 32*PAD ≡ 0 mod 32).
    const int chunk = t >> 5;           // warp id, uniform per warp
    const int lane  = t & 31;
    const int rowA  = lane;
    const int rowB  = lane + 32;
    const float* xrA = &sx[rowA * PAD];
    const float* xrB = &sx[rowB * PAD];

    float accMA = 0.0f, accLA = 0.0f;
    float accMB = 0.0f, accLB = 0.0f;

    const int gBase = chunk * GPC;
    #pragma unroll 2
    for (int i = 0; i < GPC; ++i) {
        const int g = gBase + i;
        int2 uv = sIdx[g];

        float4 k0 = sPack[g * 4 + 0];
        float4 k1 = sPack[g * 4 + 1];
        float4 k2 = sPack[g * 4 + 2];
        float4 kc = sPack[g * 4 + 3];

        float x0a = xrA[uv.x], x1a = xrA[uv.y];
        float x0b = xrB[uv.x], x1b = xrB[uv.y];

        // Row A
        {
            float p0 = fmaf(fmaf(k0.z, x1a, k0.w), x1a, fmaf(fmaf(k0.x, x0a, k0.y), x0a, kc.x));
            float p1 = fmaf(fmaf(k1.z, x1a, k1.w), x1a, fmaf(fmaf(k1.x, x0a, k1.y), x0a, kc.y));
            float p2 = fmaf(fmaf(k2.z, x1a, k2.w), x1a, fmaf(fmaf(k2.x, x0a, k2.y), x0a, kc.z));
            float mx = fmaxf(p0, fmaxf(p1, p2));
            float s  = ex2f(p0 - mx) + ex2f(p1 - mx) + ex2f(p2 - mx);
            accMA += mx;
            accLA += lg2f(s);
        }
        // Row B
        {
            float p0 = fmaf(fmaf(k0.z, x1b, k0.w), x1b, fmaf(fmaf(k0.x, x0b, k0.y), x0b, kc.x));
            float p1 = fmaf(fmaf(k1.z, x1b, k1.w), x1b, fmaf(fmaf(k1.x, x0b, k1.y), x0b, kc.y));
            float p2 = fmaf(fmaf(k2.z, x1b, k2.w), x1b, fmaf(fmaf(k2.x, x0b, k2.y), x0b, kc.z));
            float mx = fmaxf(p0, fmaxf(p1, p2));
            float s  = ex2f(p0 - mx) + ex2f(p1 - mx) + ex2f(p2 - mx);
            accMB += mx;
            accLB += lg2f(s);
        }
    }

    sRed[chunk * ROWS_PER_BLOCK + rowA] = accMA + accLA;
    sRed[chunk * ROWS_PER_BLOCK + rowB] = accMB + accLB;
    __syncthreads();

    // ---- Phase D: threads 0..63 combine the 8 chunk partials per row
    if (t < ROWS_PER_BLOCK) {
        float v = 0.0f;
        #pragma unroll
        for (int c = 0; c < CHUNKS; ++c)
            v += sRed[c * ROWS_PER_BLOCK + t];
        int gRow = rowBase + t;
        if (gRow < B) out[gRow] = v * LN2;
    }
}

extern "C" void kernel_launch(void* const* d_in, const int* in_sizes, int n_in,
                              void* d_out, int out_size)
{
    const float* x     = (const float*)d_in[0];
    const int*   perm  = (const int*)d_in[1];
    const float* means = (const float*)d_in[2];
    const float* stds  = (const float*)d_in[3];
    const float* sumw  = (const float*)d_in[4];
    float* out = (float*)d_out;

    int B = in_sizes[0] / NF;

    dim3 grid((B + ROWS_PER_BLOCK - 1) / ROWS_PER_BLOCK);
    spn_kernel<<<grid, THREADS>>>(x, perm, means, stds, sumw, out, B);
}